// round 15
// baseline (speedup 1.0000x reference)
#include <cuda_runtime.h>

// Maxwell RNN: per-row linear recurrence. One warp = one row, 8 warps per
// block, 32 chunks of 256 elements (8/lane), one-chunk register prefetch
// PLUS distance-4 L2 prefetch (prefetch.global.L2): the L2 stream keeps
// DRAM continuously fed while demand loads hit L2 (~234cyc vs ~577cyc),
// cutting the per-SM in-flight-bytes requirement ~2.5x at zero register
// cost. Zero smem, zero __syncthreads; warps free-run.
//
//   gamma_t = (1 - 0.5*dt)*gamma_{t-1} + 0.5*dt*eps_t,  gamma_{-1} = 0
//   sig_t   = 2.5*eps_t - gamma_{t-1}
// Per chunk, sig is affine in the chunk-start state: sig_j = C_j - Pp_j*g
// (C/Pp overwrite ee/dd in place). Carry: carry = P31*carry + Q31.

constexpr int Bn    = 4096;
constexpr int Tn    = 8192;
constexpr int TPB   = 256;
constexpr int WPB   = TPB / 32;        // 8 warps = 8 rows per block
constexpr int CHUNK = 256;             // elements per warp-chunk
constexpr int EPT   = 8;               // elements per lane per chunk
constexpr int NCH   = Tn / CHUNK;      // 32 chunks per row
constexpr int GRID  = Bn / WPB;        // 512 blocks
constexpr int PFD   = 4;               // L2 prefetch distance in chunks

__global__ void __launch_bounds__(TPB)
maxwell_warp_kernel(const float* __restrict__ eps, const float* __restrict__ dt,
                    float* __restrict__ out) {
    const int lane = threadIdx.x & 31;
    const int wid  = threadIdx.x >> 5;

    // 32-bit element offset of this lane's first element (33.5M < 2^32)
    unsigned off = (blockIdx.x * WPB + wid) * (unsigned)Tn + lane * EPT;

    // ---- L2 prefetch chunks 2..PFD+1 (chunks 0,1 are demand-loaded soon) ----
    if ((lane & 3) == 0) {             // 8 lanes cover 8 x 128B lines = 1KB chunk
        #pragma unroll
        for (int k = 2; k <= PFD + 1; k++) {
            const float* ape = eps + off + k * CHUNK;
            const float* apd = dt  + off + k * CHUNK;
            asm volatile("prefetch.global.L2 [%0];" :: "l"(ape));
            asm volatile("prefetch.global.L2 [%0];" :: "l"(apd));
        }
    }

    // ---- register prefetch chunk 0 ----
    float4 ce0 = *reinterpret_cast<const float4*>(eps + off);
    float4 ce1 = *reinterpret_cast<const float4*>(eps + off + 4);
    float4 cd0 = *reinterpret_cast<const float4*>(dt  + off);
    float4 cd1 = *reinterpret_cast<const float4*>(dt  + off + 4);

    float carry = 0.0f;                 // gamma entering current chunk

    #pragma unroll 2
    for (int c = 0; c < NCH; c++) {
        // ---- L2 prefetch chunk c+PFD+2 (stays PFD ahead of demand) ----
        if (c + PFD + 2 < NCH && (lane & 3) == 0) {
            unsigned poff = off + (PFD + 2) * CHUNK;
            asm volatile("prefetch.global.L2 [%0];" :: "l"(eps + poff));
            asm volatile("prefetch.global.L2 [%0];" :: "l"(dt  + poff));
        }

        // ---- register prefetch next chunk while current is processed ----
        float4 ne0, ne1, nd0, nd1;
        if (c + 1 < NCH) {
            unsigned noff = off + CHUNK;
            ne0 = *reinterpret_cast<const float4*>(eps + noff);
            ne1 = *reinterpret_cast<const float4*>(eps + noff + 4);
            nd0 = *reinterpret_cast<const float4*>(dt  + noff);
            nd1 = *reinterpret_cast<const float4*>(dt  + noff + 4);
        }

        float ee[EPT] = { ce0.x, ce0.y, ce0.z, ce0.w, ce1.x, ce1.y, ce1.z, ce1.w };
        float dd[EPT] = { cd0.x, cd0.y, cd0.z, cd0.w, cd1.x, cd1.y, cd1.z, cd1.w };

        // ---- local affine fold; rewrite (ee,dd) -> (C, Pp) in place ----
        float P = 1.0f, Q = 0.0f;
        #pragma unroll
        for (int j = 0; j < EPT; j++) {
            float e = ee[j];
            float d = dd[j];
            dd[j] = P;                      // Pp_j
            ee[j] = fmaf(2.5f, e, -Q);      // C_j
            float ad = 0.5f * d;
            float A  = 1.0f - ad;
            Q = fmaf(A, Q, ad * e);
            P = P * A;
        }

        // ---- warp-inclusive affine scan (5 shuffle steps) ----
        #pragma unroll
        for (int s = 1; s < 32; s <<= 1) {
            float Pu = __shfl_up_sync(0xFFFFFFFFu, P, s);
            float Qu = __shfl_up_sync(0xFFFFFFFFu, Q, s);
            if (lane >= s) { Q = fmaf(P, Qu, Q); P *= Pu; }
        }
        // lane-exclusive prefix -> this lane's chunk-start gamma
        float LPe = __shfl_up_sync(0xFFFFFFFFu, P, 1);
        float LQe = __shfl_up_sync(0xFFFFFFFFu, Q, 1);
        if (lane == 0) { LPe = 1.0f; LQe = 0.0f; }
        float gt = fmaf(LPe, carry, LQe);

        // ---- carry gamma to next chunk (lane-31 inclusive aggregate) ----
        float P31 = __shfl_sync(0xFFFFFFFFu, P, 31);
        float Q31 = __shfl_sync(0xFFFFFFFFu, Q, 31);
        carry = fmaf(P31, carry, Q31);

        // ---- fixup (independent FMAs) + coalesced stores ----
        float4 o0, o1;
        o0.x = fmaf(-dd[0], gt, ee[0]);
        o0.y = fmaf(-dd[1], gt, ee[1]);
        o0.z = fmaf(-dd[2], gt, ee[2]);
        o0.w = fmaf(-dd[3], gt, ee[3]);
        o1.x = fmaf(-dd[4], gt, ee[4]);
        o1.y = fmaf(-dd[5], gt, ee[5]);
        o1.z = fmaf(-dd[6], gt, ee[6]);
        o1.w = fmaf(-dd[7], gt, ee[7]);
        *reinterpret_cast<float4*>(out + off)     = o0;
        *reinterpret_cast<float4*>(out + off + 4) = o1;

        ce0 = ne0; ce1 = ne1; cd0 = nd0; cd1 = nd1;
        off += CHUNK;
    }
}

extern "C" void kernel_launch(void* const* d_in, const int* in_sizes, int n_in,
                              void* d_out, int out_size) {
    const float* eps = (const float*)d_in[0];
    const float* dt  = (const float*)d_in[1];
    float* out = (float*)d_out;

    maxwell_warp_kernel<<<GRID, TPB>>>(eps, dt, out);
}

// round 16
// speedup vs baseline: 1.3488x; 1.3488x over previous
#include <cuda_runtime.h>
#include <cstdint>

// Maxwell RNN: per-row linear recurrence. One warp = one row, each warp
// running a PRIVATE depth-4 cp.async pipeline (no block barriers, no
// inter-warp coupling): loads live in smem stages, not registers, so MLP
// is deep (8KB in flight per warp) at zero register cost.
//
//   gamma_t = (1 - 0.5*dt)*gamma_{t-1} + 0.5*dt*eps_t,  gamma_{-1} = 0
//   sig_t   = 2.5*eps_t - gamma_{t-1}
// Per chunk of 256 elems (8/lane): sig_j = C_j - Pp_j*g (C/Pp in place),
// carry = P31*carry + Q31.

constexpr int Bn    = 4096;
constexpr int Tn    = 8192;
constexpr int TPB   = 128;
constexpr int WPB   = TPB / 32;            // 4 warps = 4 rows per block
constexpr int CHUNK = 256;                 // elements per warp-chunk
constexpr int EPT   = 8;                   // elements per lane
constexpr int NCH   = Tn / CHUNK;          // 32 chunks per row
constexpr int GRID  = Bn / WPB;            // 1024 blocks
constexpr int D     = 4;                   // pipeline depth (stages)
constexpr int STAGE_B = 2048;              // 1KB eps + 1KB dt per stage

__device__ __forceinline__ uint32_t swz16(uint32_t u) {
    // XOR-swizzle 16B units within 128B rows: conflict-free LDS.128 reads
    return (u & ~7u) | ((u ^ (u >> 3)) & 7u);
}
__device__ __forceinline__ void cpasync16(uint32_t dst, const void* src) {
    asm volatile("cp.async.cg.shared.global [%0], [%1], 16;"
                 :: "r"(dst), "l"(src) : "memory");
}
__device__ __forceinline__ void cp_commit() {
    asm volatile("cp.async.commit_group;" ::: "memory");
}
template <int N>
__device__ __forceinline__ void cp_wait() {
    asm volatile("cp.async.wait_group %0;" :: "n"(N) : "memory");
}

__global__ void __launch_bounds__(TPB)
maxwell_cpasync_kernel(const float* __restrict__ eps, const float* __restrict__ dt,
                       float* __restrict__ out) {
    __shared__ __align__(16) char sm[WPB * D * STAGE_B];   // 32 KB

    const int lane = threadIdx.x & 31;
    const int wid  = threadIdx.x >> 5;

    // 32-bit element offset of this warp's row (33.5M < 2^32)
    const unsigned row0 = (blockIdx.x * WPB + wid) * (unsigned)Tn;

    char* warp_sm = sm + wid * (D * STAGE_B);
    // this lane's two 16B units per chunk (swizzled), fixed within a stage
    const uint32_t u0 = swz16(2 * lane) * 16;
    const uint32_t u1 = swz16(2 * lane + 1) * 16;
    const uint32_t g0 = 2 * lane * 16;         // matching global byte offsets
    const uint32_t g1 = g0 + 16;

    // ---- prologue: fill stages 0..D-1 (one commit group per chunk) ----
    #pragma unroll
    for (int c = 0; c < D; c++) {
        char* st = warp_sm + c * STAGE_B;
        uint32_t sE = (uint32_t)__cvta_generic_to_shared(st);
        uint32_t sD = sE + 1024;
        const char* gE = (const char*)(eps + row0 + c * CHUNK);
        const char* gD = (const char*)(dt  + row0 + c * CHUNK);
        cpasync16(sE + u0, gE + g0);
        cpasync16(sE + u1, gE + g1);
        cpasync16(sD + u0, gD + g0);
        cpasync16(sD + u1, gD + g1);
        cp_commit();
    }

    float carry = 0.0f;
    unsigned off = row0 + lane * EPT;          // this lane's output offset

    for (int c = 0; c < NCH; c++) {
        cp_wait<D - 1>();                      // oldest group (chunk c) done

        char* st = warp_sm + (c % D) * STAGE_B;
        const float4* pE = (const float4*)st;
        const float4* pD = (const float4*)(st + 1024);
        // swizzled, conflict-free LDS.128 reads of this lane's 8+8 floats
        float4 e0 = pE[u0 >> 4], e1 = pE[u1 >> 4];
        float4 d0 = pD[u0 >> 4], d1 = pD[u1 >> 4];

        // ---- refill this stage with chunk c+D; ALWAYS commit (group/chunk) ----
        if (c + D < NCH) {
            uint32_t sE = (uint32_t)__cvta_generic_to_shared(st);
            uint32_t sD = sE + 1024;
            const char* gE = (const char*)(eps + row0 + (c + D) * CHUNK);
            const char* gD = (const char*)(dt  + row0 + (c + D) * CHUNK);
            cpasync16(sE + u0, gE + g0);
            cpasync16(sE + u1, gE + g1);
            cpasync16(sD + u0, gD + g0);
            cpasync16(sD + u1, gD + g1);
        }
        cp_commit();

        float ee[EPT] = { e0.x, e0.y, e0.z, e0.w, e1.x, e1.y, e1.z, e1.w };
        float dd[EPT] = { d0.x, d0.y, d0.z, d0.w, d1.x, d1.y, d1.z, d1.w };

        // ---- local affine fold; rewrite (ee,dd) -> (C, Pp) in place ----
        float P = 1.0f, Q = 0.0f;
        #pragma unroll
        for (int j = 0; j < EPT; j++) {
            float e = ee[j];
            float d = dd[j];
            dd[j] = P;                          // Pp_j
            ee[j] = fmaf(2.5f, e, -Q);          // C_j
            float ad = 0.5f * d;
            float A  = 1.0f - ad;
            Q = fmaf(A, Q, ad * e);
            P = P * A;
        }

        // ---- warp-inclusive affine scan (5 shuffle steps) ----
        #pragma unroll
        for (int s = 1; s < 32; s <<= 1) {
            float Pu = __shfl_up_sync(0xFFFFFFFFu, P, s);
            float Qu = __shfl_up_sync(0xFFFFFFFFu, Q, s);
            if (lane >= s) { Q = fmaf(P, Qu, Q); P *= Pu; }
        }
        float LPe = __shfl_up_sync(0xFFFFFFFFu, P, 1);
        float LQe = __shfl_up_sync(0xFFFFFFFFu, Q, 1);
        if (lane == 0) { LPe = 1.0f; LQe = 0.0f; }
        float gt = fmaf(LPe, carry, LQe);

        float P31 = __shfl_sync(0xFFFFFFFFu, P, 31);
        float Q31 = __shfl_sync(0xFFFFFFFFu, Q, 31);
        carry = fmaf(P31, carry, Q31);

        // ---- fixup + coalesced stores ----
        float4 o0, o1;
        o0.x = fmaf(-dd[0], gt, ee[0]);
        o0.y = fmaf(-dd[1], gt, ee[1]);
        o0.z = fmaf(-dd[2], gt, ee[2]);
        o0.w = fmaf(-dd[3], gt, ee[3]);
        o1.x = fmaf(-dd[4], gt, ee[4]);
        o1.y = fmaf(-dd[5], gt, ee[5]);
        o1.z = fmaf(-dd[6], gt, ee[6]);
        o1.w = fmaf(-dd[7], gt, ee[7]);
        *reinterpret_cast<float4*>(out + off)     = o0;
        *reinterpret_cast<float4*>(out + off + 4) = o1;
        off += CHUNK;
    }
}

extern "C" void kernel_launch(void* const* d_in, const int* in_sizes, int n_in,
                              void* d_out, int out_size) {
    const float* eps = (const float*)d_in[0];
    const float* dt  = (const float*)d_in[1];
    float* out = (float*)d_out;

    maxwell_cpasync_kernel<<<GRID, TPB>>>(eps, dt, out);
}